// round 14
// baseline (speedup 1.0000x reference)
#include <cuda_runtime.h>

// Problem constants (fixed shapes from reference setup_inputs)
#define NS   262144      // B*T*C samples
#define NEL  16777216    // B*T*C*F elements for reconstruction loss
#define KK   8           // mixture components
#define DD   8           // latent dim
#define NTRI 36          // D*(D+1)/2 upper-triangular entries
#define MPK  45          // per-k moment slots: gsum(1) + sz(8) + s2(36)

#define LAMBDA_ENERGY 0.1
#define LAMBDA_COV    0.005

// Co-residency budget (64K regs/SM):
//   reconst 4/SM @32regs = 32K  +  moments 2/SM @<=51regs = 26K  -> 58K OK
//   after moments: energy 1/SM @<=64regs = 16K + reconst 32K     -> 48K OK
#define RECONST_BLOCKS 592
#define MOMENT_BLOCKS  296
#define ENERGY_BLOCKS  148
#define DONE_TARGET    (RECONST_BLOCKS + ENERGY_BLOCKS)

// ---------------- device scratch (zero-initialized at module load; the
// finalizing block re-zeroes everything dirtied each replay) ----------------
__device__ double g_mom[KK * MPK];   // [k][0]=gsum, [1..8]=sum(g*z), [9..44]=sum(g*zi*zj)
__device__ double g_reconst;
__device__ double g_energy;
__device__ double g_base;            // lambda_cov*cov_diag
__device__ float  g_w2[KK * NTRI];
__device__ float  g_bv[KK * DD];
__device__ float  g_cst[KK];
__device__ unsigned g_mctr;          // moments last-block counter
__device__ unsigned g_done;          // completion counter (reconst + energy)

// upper-tri row starts for D=8: t(i,j) = TRI_ROW[i] + (j - i), j >= i
__device__ __constant__ int TRI_ROW[8] = {0, 8, 15, 21, 26, 30, 33, 35};

__device__ __forceinline__ float warp_reduce(float v) {
#pragma unroll
    for (int o = 16; o > 0; o >>= 1) v += __shfl_xor_sync(0xFFFFFFFFu, v, o);
    return v;
}

__device__ __forceinline__ void finish_and_maybe_finalize(float* out) {
    __shared__ unsigned s_last;
    if (threadIdx.x == 0) {
        __threadfence();
        unsigned prev = atomicAdd(&g_done, 1u);
        s_last = (prev == (unsigned)(DONE_TARGET - 1)) ? 1u : 0u;
    }
    __syncthreads();
    if (s_last) {
        if (threadIdx.x == 0) {
            __threadfence();
            double rm = g_reconst / (double)NEL;
            double e  = *((volatile double*)&g_energy);
            out[0] = (float)(rm + g_base + LAMBDA_ENERGY * (e / (double)NS));
            g_reconst = 0.0;
            g_energy = 0.0;
            g_done = 0u;
        }
        for (int i = threadIdx.x; i < KK * MPK; i += blockDim.x) g_mom[i] = 0.0;
    }
}

// ---------------- reconst: pure HBM stream, 4 blocks/SM --------------------
__global__ void __launch_bounds__(256, 4) reconst_kernel(
    const float4* __restrict__ x, const float4* __restrict__ xh,
    float* __restrict__ out) {
    const int n4 = NEL / 4;
    float acc0 = 0.0f, acc1 = 0.0f;
    int i = blockIdx.x * 256 + threadIdx.x;
    const int stride = RECONST_BLOCKS * 256;
    for (; i + stride < n4; i += 2 * stride) {
        float4 a0 = x[i], b0 = xh[i];
        float4 a1 = x[i + stride], b1 = xh[i + stride];
        float d;
        d = b0.x - a0.x; acc0 = fmaf(d, d, acc0);
        d = b0.y - a0.y; acc0 = fmaf(d, d, acc0);
        d = b0.z - a0.z; acc0 = fmaf(d, d, acc0);
        d = b0.w - a0.w; acc0 = fmaf(d, d, acc0);
        d = b1.x - a1.x; acc1 = fmaf(d, d, acc1);
        d = b1.y - a1.y; acc1 = fmaf(d, d, acc1);
        d = b1.z - a1.z; acc1 = fmaf(d, d, acc1);
        d = b1.w - a1.w; acc1 = fmaf(d, d, acc1);
    }
    for (; i < n4; i += stride) {
        float4 a = x[i], b = xh[i];
        float d;
        d = b.x - a.x; acc0 = fmaf(d, d, acc0);
        d = b.y - a.y; acc0 = fmaf(d, d, acc0);
        d = b.z - a.z; acc0 = fmaf(d, d, acc0);
        d = b.w - a.w; acc0 = fmaf(d, d, acc0);
    }
    __shared__ float red[8];
    float v = warp_reduce(acc0 + acc1);
    int lane = threadIdx.x & 31, wid = threadIdx.x >> 5;
    if (lane == 0) red[wid] = v;
    __syncthreads();
    if (threadIdx.x == 0) {
        float s = 0.0f;
#pragma unroll
        for (int w = 0; w < 8; w++) s += red[w];
        atomicAdd(&g_reconst, (double)s);
    }
    finish_and_maybe_finalize(out);
}

// ---------------- moments: 4-way triangle split, <=51 regs -----------------
// Quarter q owns triangle rows {q, 7-q}: 9 s2 entries + sz rows {q, 7-q}.
// Warp w: quarter = w&3, sample-set = w>>2. lane&7 = component k,
// lane>>3 = sample subgroup. Block covers 8 sample slots (4 lanes x 2 sets).
__global__ void __launch_bounds__(256, 5) moments_kernel(
    const float* __restrict__ z, const float* __restrict__ gamma) {
    const int lane = threadIdx.x & 31;
    const int k = lane & 7;
    const int warp = threadIdx.x >> 5;     // 0..7
    const int q = warp & 3;                // quarter (uniform per warp)
    const int wset = warp >> 2;            // sample-set 0/1 (uniform per warp)
    const int ra = q;                      // first owned row
    const int rb = 7 - q;                  // second owned row
    const int na = 8 - ra;                 // entries in row ra
    // slot covers samples: 8 per block
    const int slot = blockIdx.x * 8 + wset * 4 + (lane >> 3);
    const int stride = MOMENT_BLOCKS * 8;

    float gs = 0.0f;
    float sza = 0.0f, szb = 0.0f;
    float s2[9];
#pragma unroll
    for (int t = 0; t < 9; t++) s2[t] = 0.0f;

    for (int n = slot; n < NS; n += stride) {
        float4 z0 = *reinterpret_cast<const float4*>(z + (size_t)n * 8);
        float4 z1 = *reinterpret_cast<const float4*>(z + (size_t)n * 8 + 4);
        float zz[8] = {z0.x, z0.y, z0.z, z0.w, z1.x, z1.y, z1.z, z1.w};
        float g = __ldg(gamma + (size_t)n * 8 + k);
        if (q == 0) gs += g;
        float gza = g * zz[ra];
        float gzb = g * zz[rb];
        sza += gza; szb += gzb;
#pragma unroll
        for (int j = 0; j < 8; j++)
            if (j >= ra && j - ra < na) s2[j - ra] = fmaf(gza, zz[j], s2[j - ra]);
#pragma unroll
        for (int j = 0; j < 8; j++)
            if (j >= rb) s2[na + (j - rb)] = fmaf(gzb, zz[j], s2[na + (j - rb)]);
    }

    // combine the 4 lane-groups in this warp sharing (k, quarter)
    const unsigned m = 0xFFFFFFFFu;
    gs  += __shfl_xor_sync(m, gs, 8);   gs  += __shfl_xor_sync(m, gs, 16);
    sza += __shfl_xor_sync(m, sza, 8);  sza += __shfl_xor_sync(m, sza, 16);
    szb += __shfl_xor_sync(m, szb, 8);  szb += __shfl_xor_sync(m, szb, 16);
#pragma unroll
    for (int t = 0; t < 9; t++) {
        s2[t] += __shfl_xor_sync(m, s2[t], 8);
        s2[t] += __shfl_xor_sync(m, s2[t], 16);
    }

    // each warp-set writes a complete bank (quarters 0-3 cover all slots)
    __shared__ float sacc[2][KK * MPK];   // 2.9 KB
    if (lane < 8) {
        float* p = &sacc[wset][k * MPK];
        if (q == 0) p[0] = gs;
        p[1 + ra] = sza;
        p[1 + rb] = szb;
        const int ta = TRI_ROW[ra];
        const int tb = TRI_ROW[rb];
#pragma unroll
        for (int t = 0; t < 9; t++) {
            int dst = (t < na) ? (ta + t) : (tb + (t - na));
            p[9 + dst] = s2[t];
        }
    }
    __syncthreads();

    for (int i = threadIdx.x; i < KK * MPK; i += 256)
        atomicAdd(&g_mom[i], (double)(sacc[0][i] + sacc[1][i]));

    // ---- last block runs stats inline (warp per component) ----
    __shared__ bool is_last;
    __threadfence();
    __syncthreads();
    if (threadIdx.x == 0) {
        unsigned prev = atomicAdd(&g_mctr, 1u);
        is_last = (prev == (unsigned)(gridDim.x - 1));
        if (is_last) g_mctr = 0u;      // reset for next replay
    }
    __syncthreads();
    if (!is_last) return;
    __threadfence();                    // acquire all g_mom writes

    {
        const int w = warp;             // component k
        const int r = lane;             // rows live in lanes 0..7
        __shared__ float s_cd[8];

        const double* mo = g_mom + w * MPK;
        const float gsf = (float)mo[0];
        const float rgs = 1.0f / gsf;

        float mu[8];
#pragma unroll
        for (int j = 0; j < 8; j++) mu[j] = (float)mo[1 + j] * rgs;

        float ar[8], ir[8];
        float cd = 0.0f;
        if (r < 8) {
#pragma unroll
            for (int j = 0; j < 8; j++) {
                int i0 = r < j ? r : j;
                int j0 = r < j ? j : r;
                int t = TRI_ROW[i0] + (j0 - i0);
                ar[j] = fmaf(-mu[r], mu[j], (float)mo[9 + t] * rgs);
                ir[j] = (r == j) ? 1.0f : 0.0f;
            }
            ar[r] += 1e-12f;            // EPS*I, matches reference
            cd = 1.0f / ar[r];
        } else {
#pragma unroll
            for (int j = 0; j < 8; j++) { ar[j] = (r == j + 24) ? 1.0f : 0.0f; ir[j] = 0.0f; }
        }

        float det = 1.0f;
#pragma unroll
        for (int p = 0; p < 8; p++) {
            float piv = __shfl_sync(m, ar[p], p);
            det *= piv;
            float rc = 1.0f / piv;
            float par[8], pir[8];
#pragma unroll
            for (int j = 0; j < 8; j++) par[j] = __shfl_sync(m, ar[j], p) * rc;
#pragma unroll
            for (int j = 0; j < 8; j++) pir[j] = __shfl_sync(m, ir[j], p) * rc;
            float f = ar[p];
            if (r == p) {
#pragma unroll
                for (int j = 0; j < 8; j++) { ar[j] = par[j]; ir[j] = pir[j]; }
            } else {
#pragma unroll
                for (int j = 0; j < 8; j++) {
                    ar[j] = fmaf(-f, par[j], ar[j]);
                    ir[j] = fmaf(-f, pir[j], ir[j]);
                }
            }
        }

        float cstp = 0.0f;
        if (r < 8) {
#pragma unroll
            for (int j = 0; j < 8; j++) {
                if (j >= r) {
                    int t = TRI_ROW[r] + (j - r);
                    g_w2[w * NTRI + t] = (j == r) ? (-0.5f * ir[r]) : (-ir[j]);
                }
            }
            float b = 0.0f;
#pragma unroll
            for (int j = 0; j < 8; j++) b = fmaf(ir[j], mu[j], b);
            g_bv[w * DD + r] = b;
            cstp = b * mu[r];
        }
#pragma unroll
        for (int o = 4; o > 0; o >>= 1) {
            cstp += __shfl_xor_sync(m, cstp, o);
            cd   += __shfl_xor_sync(m, cd, o);
        }
        if (r == 0) {
            float phi = gsf * (1.0f / (float)NS);
            float ck = phi / (39.478417604357434f * sqrtf(sqrtf(det)));
            g_cst[w] = -0.5f * cstp + logf(ck);
            s_cd[w] = cd;
        }
        __syncthreads();
        if (threadIdx.x == 0) {
            float cdt = 0.0f;
#pragma unroll
            for (int i = 0; i < 8; i++) cdt += s_cd[i];
            g_base = LAMBDA_COV * (double)cdt;
        }
    }
}

// ---------------- energy: 1 block/SM, co-resident with reconst -------------
__global__ void __launch_bounds__(256, 2) energy_kernel(const float* __restrict__ z,
                                                        float* __restrict__ out) {
    const int lane = threadIdx.x & 31;
    const int k = lane & 7;

    float w[NTRI], bv[DD], cst;
#pragma unroll
    for (int t = 0; t < NTRI; t++) w[t] = g_w2[k * NTRI + t];
#pragma unroll
    for (int i = 0; i < DD; i++) bv[i] = g_bv[k * DD + i];
    cst = g_cst[k];

    const int slot = (blockIdx.x * blockDim.x + threadIdx.x) >> 3;
    const int stride = (gridDim.x * blockDim.x) >> 3;
    const unsigned m = 0xFFFFFFFFu;

    float acc = 0.0f;
    int n = slot;
    for (; n + stride < NS; n += 2 * stride) {
        float4 a0 = *reinterpret_cast<const float4*>(z + (size_t)n * 8);
        float4 a1 = *reinterpret_cast<const float4*>(z + (size_t)n * 8 + 4);
        float4 b0 = *reinterpret_cast<const float4*>(z + (size_t)(n + stride) * 8);
        float4 b1 = *reinterpret_cast<const float4*>(z + (size_t)(n + stride) * 8 + 4);
        {
            float zz[8] = {a0.x, a0.y, a0.z, a0.w, a1.x, a1.y, a1.z, a1.w};
            float qv = cst;
            int t = 0;
#pragma unroll
            for (int i = 0; i < 8; i++) {
                float row = bv[i];
#pragma unroll
                for (int j = i; j < 8; j++) { row = fmaf(w[t], zz[j], row); t++; }
                qv = fmaf(zz[i], row, qv);
            }
            float e = __expf(qv);
            e += __shfl_xor_sync(m, e, 1);
            e += __shfl_xor_sync(m, e, 2);
            e += __shfl_xor_sync(m, e, 4);
            if (k == 0) acc += -__logf(e + 1e-12f);
        }
        {
            float zz[8] = {b0.x, b0.y, b0.z, b0.w, b1.x, b1.y, b1.z, b1.w};
            float qv = cst;
            int t = 0;
#pragma unroll
            for (int i = 0; i < 8; i++) {
                float row = bv[i];
#pragma unroll
                for (int j = i; j < 8; j++) { row = fmaf(w[t], zz[j], row); t++; }
                qv = fmaf(zz[i], row, qv);
            }
            float e = __expf(qv);
            e += __shfl_xor_sync(m, e, 1);
            e += __shfl_xor_sync(m, e, 2);
            e += __shfl_xor_sync(m, e, 4);
            if (k == 0) acc += -__logf(e + 1e-12f);
        }
    }
    for (; n < NS; n += stride) {
        float4 a0 = *reinterpret_cast<const float4*>(z + (size_t)n * 8);
        float4 a1 = *reinterpret_cast<const float4*>(z + (size_t)n * 8 + 4);
        float zz[8] = {a0.x, a0.y, a0.z, a0.w, a1.x, a1.y, a1.z, a1.w};
        float qv = cst;
        int t = 0;
#pragma unroll
        for (int i = 0; i < 8; i++) {
            float row = bv[i];
#pragma unroll
            for (int j = i; j < 8; j++) { row = fmaf(w[t], zz[j], row); t++; }
            qv = fmaf(zz[i], row, qv);
        }
        float e = __expf(qv);
        e += __shfl_xor_sync(m, e, 1);
        e += __shfl_xor_sync(m, e, 2);
        e += __shfl_xor_sync(m, e, 4);
        if (k == 0) acc += -__logf(e + 1e-12f);
    }

    __shared__ float red[8];
    float v = warp_reduce(acc);
    int wid = threadIdx.x >> 5;
    if (lane == 0) red[wid] = v;
    __syncthreads();
    if (threadIdx.x == 0) {
        float s = 0.0f;
#pragma unroll
        for (int i = 0; i < 8; i++) s += red[i];
        atomicAdd(&g_energy, (double)s);
    }
    finish_and_maybe_finalize(out);
}

// ---------------- launch: moments CONCURRENT with reconst ------------------
static cudaStream_t s_side = nullptr;
static cudaEvent_t s_fork = nullptr, s_join = nullptr;

extern "C" void kernel_launch(void* const* d_in, const int* in_sizes, int n_in,
                              void* d_out, int out_size) {
    const float* x     = (const float*)d_in[0];
    const float* xh    = (const float*)d_in[1];
    const float* z     = (const float*)d_in[2];
    const float* gamma = (const float*)d_in[3];
    float* out = (float*)d_out;

    if (s_side == nullptr) {
        cudaStreamCreateWithFlags(&s_side, cudaStreamNonBlocking);
        cudaEventCreateWithFlags(&s_fork, cudaEventDisableTiming);
        cudaEventCreateWithFlags(&s_join, cudaEventDisableTiming);
    }

    // fork: moments (low-reg, 2/SM) runs BESIDE reconst (4/SM) from t=0;
    // energy (1/SM) follows moments on the side stream, also co-resident.
    cudaEventRecord(s_fork, 0);
    cudaStreamWaitEvent(s_side, s_fork, 0);
    moments_kernel<<<MOMENT_BLOCKS, 256, 0, s_side>>>(z, gamma);
    energy_kernel<<<ENERGY_BLOCKS, 256, 0, s_side>>>(z, out);
    reconst_kernel<<<RECONST_BLOCKS, 256>>>((const float4*)x, (const float4*)xh, out);
    cudaEventRecord(s_join, s_side);
    cudaStreamWaitEvent(0, s_join, 0);
}

// round 15
// speedup vs baseline: 2.2093x; 2.2093x over previous
#include <cuda_runtime.h>

// Problem constants (fixed shapes from reference setup_inputs)
#define NS   262144      // B*T*C samples
#define NEL  16777216    // B*T*C*F elements for reconstruction loss
#define KK   8           // mixture components
#define DD   8           // latent dim
#define NTRI 36          // D*(D+1)/2 upper-triangular entries
#define MPK  45          // per-k moment slots: gsum(1) + sz(8) + s2(36)

#define LAMBDA_ENERGY 0.1
#define LAMBDA_COV    0.005

// Co-residency budget (64K regs/SM):
//   reconst 4/SM @32regs = 32K  +  moments 2/SM @~40regs = 24.6K -> 57K OK
//   after moments: energy 2/SM @<=64regs = 32K + reconst 32K     -> 64K fits
#define RECONST_BLOCKS 592
#define MOMENT_BLOCKS  296
#define ENERGY_BLOCKS  296
#define DONE_TARGET    (RECONST_BLOCKS + ENERGY_BLOCKS)

// ---------------- device scratch (zero-initialized at module load; the
// finalizing block re-zeroes everything dirtied each replay) ----------------
__device__ double g_mom[KK * MPK];   // [k][0]=gsum, [1..8]=sum(g*z), [9..44]=sum(g*zi*zj)
__device__ double g_reconst;
__device__ double g_energy;
__device__ double g_base;            // lambda_cov*cov_diag
__device__ float  g_w2[KK * NTRI];
__device__ float  g_bv[KK * DD];
__device__ float  g_cst[KK];
__device__ unsigned g_mctr;          // moments last-block counter
__device__ unsigned g_done;          // completion counter (reconst + energy)

// upper-tri row starts for D=8: t(i,j) = TRI_ROW[i] + (j - i), j >= i
__device__ __constant__ int TRI_ROW[8] = {0, 8, 15, 21, 26, 30, 33, 35};

__device__ __forceinline__ float warp_reduce(float v) {
#pragma unroll
    for (int o = 16; o > 0; o >>= 1) v += __shfl_xor_sync(0xFFFFFFFFu, v, o);
    return v;
}

__device__ __forceinline__ void finish_and_maybe_finalize(float* out) {
    __shared__ unsigned s_last;
    if (threadIdx.x == 0) {
        __threadfence();
        unsigned prev = atomicAdd(&g_done, 1u);
        s_last = (prev == (unsigned)(DONE_TARGET - 1)) ? 1u : 0u;
    }
    __syncthreads();
    if (s_last) {
        if (threadIdx.x == 0) {
            __threadfence();
            double rm = g_reconst / (double)NEL;
            double e  = *((volatile double*)&g_energy);
            out[0] = (float)(rm + g_base + LAMBDA_ENERGY * (e / (double)NS));
            g_reconst = 0.0;
            g_energy = 0.0;
            g_done = 0u;
        }
        for (int i = threadIdx.x; i < KK * MPK; i += blockDim.x) g_mom[i] = 0.0;
    }
}

// ---------------- reconst: pure HBM stream, 4 blocks/SM --------------------
__global__ void __launch_bounds__(256, 4) reconst_kernel(
    const float4* __restrict__ x, const float4* __restrict__ xh,
    float* __restrict__ out) {
    const int n4 = NEL / 4;
    float acc0 = 0.0f, acc1 = 0.0f;
    int i = blockIdx.x * 256 + threadIdx.x;
    const int stride = RECONST_BLOCKS * 256;
    for (; i + stride < n4; i += 2 * stride) {
        float4 a0 = x[i], b0 = xh[i];
        float4 a1 = x[i + stride], b1 = xh[i + stride];
        float d;
        d = b0.x - a0.x; acc0 = fmaf(d, d, acc0);
        d = b0.y - a0.y; acc0 = fmaf(d, d, acc0);
        d = b0.z - a0.z; acc0 = fmaf(d, d, acc0);
        d = b0.w - a0.w; acc0 = fmaf(d, d, acc0);
        d = b1.x - a1.x; acc1 = fmaf(d, d, acc1);
        d = b1.y - a1.y; acc1 = fmaf(d, d, acc1);
        d = b1.z - a1.z; acc1 = fmaf(d, d, acc1);
        d = b1.w - a1.w; acc1 = fmaf(d, d, acc1);
    }
    for (; i < n4; i += stride) {
        float4 a = x[i], b = xh[i];
        float d;
        d = b.x - a.x; acc0 = fmaf(d, d, acc0);
        d = b.y - a.y; acc0 = fmaf(d, d, acc0);
        d = b.z - a.z; acc0 = fmaf(d, d, acc0);
        d = b.w - a.w; acc0 = fmaf(d, d, acc0);
    }
    __shared__ float red[8];
    float v = warp_reduce(acc0 + acc1);
    int lane = threadIdx.x & 31, wid = threadIdx.x >> 5;
    if (lane == 0) red[wid] = v;
    __syncthreads();
    if (threadIdx.x == 0) {
        float s = 0.0f;
#pragma unroll
        for (int w = 0; w < 8; w++) s += red[w];
        atomicAdd(&g_reconst, (double)s);
    }
    finish_and_maybe_finalize(out);
}

// ---------------- moments: templated 4-way triangle split ------------------
// Quarter Q (compile-time!) owns triangle rows {Q, 7-Q}: (8-Q)+(Q+1)=9 s2
// entries + sz rows {Q, 7-Q} (+gs for Q=0). All zz[] indices compile-time ->
// everything stays in registers (the round-14 runtime-index version spilled).
template<int Q>
__device__ __forceinline__ void mom_loop(
    const float* __restrict__ z, const float* __restrict__ gamma,
    int slot, int stride, int k,
    float& gs, float& sza, float& szb, float (&s2)[9]) {
    constexpr int RA = Q;
    constexpr int RB = 7 - Q;
    constexpr int NA = 8 - Q;           // entries in row RA
    for (int n = slot; n < NS; n += stride) {
        float4 z0 = *reinterpret_cast<const float4*>(z + (size_t)n * 8);
        float4 z1 = *reinterpret_cast<const float4*>(z + (size_t)n * 8 + 4);
        float zz[8] = {z0.x, z0.y, z0.z, z0.w, z1.x, z1.y, z1.z, z1.w};
        float g = __ldg(gamma + (size_t)n * 8 + k);
        if (Q == 0) gs += g;
        float gza = g * zz[RA];
        float gzb = g * zz[RB];
        sza += gza; szb += gzb;
#pragma unroll
        for (int j = RA; j < 8; j++) s2[j - RA] = fmaf(gza, zz[j], s2[j - RA]);
#pragma unroll
        for (int j = RB; j < 8; j++) s2[NA + (j - RB)] = fmaf(gzb, zz[j], s2[NA + (j - RB)]);
    }
}

__global__ void __launch_bounds__(256, 5) moments_kernel(
    const float* __restrict__ z, const float* __restrict__ gamma) {
    const int lane = threadIdx.x & 31;
    const int k = lane & 7;
    const int warp = threadIdx.x >> 5;     // 0..7
    const int q = warp & 3;                // quarter (uniform per warp)
    const int wset = warp >> 2;            // sample-set 0/1 (uniform per warp)
    const int ra = q;
    const int rb = 7 - q;
    const int na = 8 - ra;
    const int slot = blockIdx.x * 8 + wset * 4 + (lane >> 3);
    const int stride = MOMENT_BLOCKS * 8;

    float gs = 0.0f, sza = 0.0f, szb = 0.0f;
    float s2[9];
#pragma unroll
    for (int t = 0; t < 9; t++) s2[t] = 0.0f;

    switch (q) {                            // uniform per warp, loop hoisted
        case 0: mom_loop<0>(z, gamma, slot, stride, k, gs, sza, szb, s2); break;
        case 1: mom_loop<1>(z, gamma, slot, stride, k, gs, sza, szb, s2); break;
        case 2: mom_loop<2>(z, gamma, slot, stride, k, gs, sza, szb, s2); break;
        default: mom_loop<3>(z, gamma, slot, stride, k, gs, sza, szb, s2); break;
    }

    // combine the 4 lane-groups in this warp sharing (k, quarter)
    const unsigned m = 0xFFFFFFFFu;
    gs  += __shfl_xor_sync(m, gs, 8);   gs  += __shfl_xor_sync(m, gs, 16);
    sza += __shfl_xor_sync(m, sza, 8);  sza += __shfl_xor_sync(m, sza, 16);
    szb += __shfl_xor_sync(m, szb, 8);  szb += __shfl_xor_sync(m, szb, 16);
#pragma unroll
    for (int t = 0; t < 9; t++) {
        s2[t] += __shfl_xor_sync(m, s2[t], 8);
        s2[t] += __shfl_xor_sync(m, s2[t], 16);
    }

    // each warp-set writes a complete bank (quarters 0-3 cover all slots)
    __shared__ float sacc[2][KK * MPK];   // 2.9 KB
    if (lane < 8) {
        float* p = &sacc[wset][k * MPK];
        if (q == 0) p[0] = gs;
        p[1 + ra] = sza;                  // shared-store addresses may be runtime
        p[1 + rb] = szb;
        const int ta = TRI_ROW[ra];
        const int tb = TRI_ROW[rb];
#pragma unroll
        for (int t = 0; t < 9; t++) {     // s2[t] reads are compile-time
            int dst = (t < na) ? (ta + t) : (tb + (t - na));
            p[9 + dst] = s2[t];
        }
    }
    __syncthreads();

    for (int i = threadIdx.x; i < KK * MPK; i += 256)
        atomicAdd(&g_mom[i], (double)(sacc[0][i] + sacc[1][i]));

    // ---- last block runs stats inline (warp per component) ----
    __shared__ bool is_last;
    __threadfence();
    __syncthreads();
    if (threadIdx.x == 0) {
        unsigned prev = atomicAdd(&g_mctr, 1u);
        is_last = (prev == (unsigned)(gridDim.x - 1));
        if (is_last) g_mctr = 0u;      // reset for next replay
    }
    __syncthreads();
    if (!is_last) return;
    __threadfence();                    // acquire all g_mom writes

    {
        const int w = warp;             // component k
        const int r = lane;             // rows live in lanes 0..7
        __shared__ float s_cd[8];

        const double* mo = g_mom + w * MPK;
        const float gsf = (float)mo[0];
        const float rgs = 1.0f / gsf;

        float mu[8];
#pragma unroll
        for (int j = 0; j < 8; j++) mu[j] = (float)mo[1 + j] * rgs;

        float ar[8], ir[8];
        float cd = 0.0f;
        if (r < 8) {
#pragma unroll
            for (int j = 0; j < 8; j++) {
                int i0 = r < j ? r : j;
                int j0 = r < j ? j : r;
                int t = TRI_ROW[i0] + (j0 - i0);
                ar[j] = fmaf(-mu[r], mu[j], (float)mo[9 + t] * rgs);
                ir[j] = (r == j) ? 1.0f : 0.0f;
            }
            ar[r] += 1e-12f;            // EPS*I, matches reference
            cd = 1.0f / ar[r];
        } else {
#pragma unroll
            for (int j = 0; j < 8; j++) { ar[j] = (r == j + 24) ? 1.0f : 0.0f; ir[j] = 0.0f; }
        }

        float det = 1.0f;
#pragma unroll
        for (int p = 0; p < 8; p++) {
            float piv = __shfl_sync(m, ar[p], p);
            det *= piv;
            float rc = 1.0f / piv;
            float par[8], pir[8];
#pragma unroll
            for (int j = 0; j < 8; j++) par[j] = __shfl_sync(m, ar[j], p) * rc;
#pragma unroll
            for (int j = 0; j < 8; j++) pir[j] = __shfl_sync(m, ir[j], p) * rc;
            float f = ar[p];
            if (r == p) {
#pragma unroll
                for (int j = 0; j < 8; j++) { ar[j] = par[j]; ir[j] = pir[j]; }
            } else {
#pragma unroll
                for (int j = 0; j < 8; j++) {
                    ar[j] = fmaf(-f, par[j], ar[j]);
                    ir[j] = fmaf(-f, pir[j], ir[j]);
                }
            }
        }

        float cstp = 0.0f;
        if (r < 8) {
#pragma unroll
            for (int j = 0; j < 8; j++) {
                if (j >= r) {
                    int t = TRI_ROW[r] + (j - r);
                    g_w2[w * NTRI + t] = (j == r) ? (-0.5f * ir[r]) : (-ir[j]);
                }
            }
            float b = 0.0f;
#pragma unroll
            for (int j = 0; j < 8; j++) b = fmaf(ir[j], mu[j], b);
            g_bv[w * DD + r] = b;
            cstp = b * mu[r];
        }
#pragma unroll
        for (int o = 4; o > 0; o >>= 1) {
            cstp += __shfl_xor_sync(m, cstp, o);
            cd   += __shfl_xor_sync(m, cd, o);
        }
        if (r == 0) {
            float phi = gsf * (1.0f / (float)NS);
            float ck = phi / (39.478417604357434f * sqrtf(sqrtf(det)));
            g_cst[w] = -0.5f * cstp + logf(ck);
            s_cd[w] = cd;
        }
        __syncthreads();
        if (threadIdx.x == 0) {
            float cdt = 0.0f;
#pragma unroll
            for (int i = 0; i < 8; i++) cdt += s_cd[i];
            g_base = LAMBDA_COV * (double)cdt;
        }
    }
}

// ---------------- energy: 2 blocks/SM, co-resident with reconst ------------
__global__ void __launch_bounds__(256, 2) energy_kernel(const float* __restrict__ z,
                                                        float* __restrict__ out) {
    const int lane = threadIdx.x & 31;
    const int k = lane & 7;

    float w[NTRI], bv[DD], cst;
#pragma unroll
    for (int t = 0; t < NTRI; t++) w[t] = g_w2[k * NTRI + t];
#pragma unroll
    for (int i = 0; i < DD; i++) bv[i] = g_bv[k * DD + i];
    cst = g_cst[k];

    const int slot = (blockIdx.x * blockDim.x + threadIdx.x) >> 3;
    const int stride = (gridDim.x * blockDim.x) >> 3;
    const unsigned m = 0xFFFFFFFFu;

    float acc = 0.0f;
    int n = slot;
    for (; n + stride < NS; n += 2 * stride) {
        float4 a0 = *reinterpret_cast<const float4*>(z + (size_t)n * 8);
        float4 a1 = *reinterpret_cast<const float4*>(z + (size_t)n * 8 + 4);
        float4 b0 = *reinterpret_cast<const float4*>(z + (size_t)(n + stride) * 8);
        float4 b1 = *reinterpret_cast<const float4*>(z + (size_t)(n + stride) * 8 + 4);
        {
            float zz[8] = {a0.x, a0.y, a0.z, a0.w, a1.x, a1.y, a1.z, a1.w};
            float qv = cst;
            int t = 0;
#pragma unroll
            for (int i = 0; i < 8; i++) {
                float row = bv[i];
#pragma unroll
                for (int j = i; j < 8; j++) { row = fmaf(w[t], zz[j], row); t++; }
                qv = fmaf(zz[i], row, qv);
            }
            float e = __expf(qv);
            e += __shfl_xor_sync(m, e, 1);
            e += __shfl_xor_sync(m, e, 2);
            e += __shfl_xor_sync(m, e, 4);
            if (k == 0) acc += -__logf(e + 1e-12f);
        }
        {
            float zz[8] = {b0.x, b0.y, b0.z, b0.w, b1.x, b1.y, b1.z, b1.w};
            float qv = cst;
            int t = 0;
#pragma unroll
            for (int i = 0; i < 8; i++) {
                float row = bv[i];
#pragma unroll
                for (int j = i; j < 8; j++) { row = fmaf(w[t], zz[j], row); t++; }
                qv = fmaf(zz[i], row, qv);
            }
            float e = __expf(qv);
            e += __shfl_xor_sync(m, e, 1);
            e += __shfl_xor_sync(m, e, 2);
            e += __shfl_xor_sync(m, e, 4);
            if (k == 0) acc += -__logf(e + 1e-12f);
        }
    }
    for (; n < NS; n += stride) {
        float4 a0 = *reinterpret_cast<const float4*>(z + (size_t)n * 8);
        float4 a1 = *reinterpret_cast<const float4*>(z + (size_t)n * 8 + 4);
        float zz[8] = {a0.x, a0.y, a0.z, a0.w, a1.x, a1.y, a1.z, a1.w};
        float qv = cst;
        int t = 0;
#pragma unroll
        for (int i = 0; i < 8; i++) {
            float row = bv[i];
#pragma unroll
            for (int j = i; j < 8; j++) { row = fmaf(w[t], zz[j], row); t++; }
            qv = fmaf(zz[i], row, qv);
        }
        float e = __expf(qv);
        e += __shfl_xor_sync(m, e, 1);
        e += __shfl_xor_sync(m, e, 2);
        e += __shfl_xor_sync(m, e, 4);
        if (k == 0) acc += -__logf(e + 1e-12f);
    }

    __shared__ float red[8];
    float v = warp_reduce(acc);
    int wid = threadIdx.x >> 5;
    if (lane == 0) red[wid] = v;
    __syncthreads();
    if (threadIdx.x == 0) {
        float s = 0.0f;
#pragma unroll
        for (int i = 0; i < 8; i++) s += red[i];
        atomicAdd(&g_energy, (double)s);
    }
    finish_and_maybe_finalize(out);
}

// ---------------- launch: moments CONCURRENT with reconst ------------------
static cudaStream_t s_side = nullptr;
static cudaEvent_t s_fork = nullptr, s_join = nullptr;

extern "C" void kernel_launch(void* const* d_in, const int* in_sizes, int n_in,
                              void* d_out, int out_size) {
    const float* x     = (const float*)d_in[0];
    const float* xh    = (const float*)d_in[1];
    const float* z     = (const float*)d_in[2];
    const float* gamma = (const float*)d_in[3];
    float* out = (float*)d_out;

    if (s_side == nullptr) {
        cudaStreamCreateWithFlags(&s_side, cudaStreamNonBlocking);
        cudaEventCreateWithFlags(&s_fork, cudaEventDisableTiming);
        cudaEventCreateWithFlags(&s_join, cudaEventDisableTiming);
    }

    // fork: moments (low-reg, 2/SM) runs BESIDE reconst (4/SM) from t=0;
    // energy follows moments on the side stream, also co-resident.
    cudaEventRecord(s_fork, 0);
    cudaStreamWaitEvent(s_side, s_fork, 0);
    moments_kernel<<<MOMENT_BLOCKS, 256, 0, s_side>>>(z, gamma);
    energy_kernel<<<ENERGY_BLOCKS, 256, 0, s_side>>>(z, out);
    reconst_kernel<<<RECONST_BLOCKS, 256>>>((const float4*)x, (const float4*)xh, out);
    cudaEventRecord(s_join, s_side);
    cudaStreamWaitEvent(0, s_join, 0);
}

// round 16
// speedup vs baseline: 2.7977x; 1.2663x over previous
#include <cuda_runtime.h>

// Problem constants (fixed shapes from reference setup_inputs)
#define NS   262144      // B*T*C samples
#define NEL  16777216    // B*T*C*F elements for reconstruction loss
#define N4   (NEL / 4)   // float4 elements
#define SPLIT_N4 786432  // first 18.75% of float4s handled by reconstA (window 1)
#define KK   8           // mixture components
#define DD   8           // latent dim
#define NTRI 36          // D*(D+1)/2 upper-triangular entries
#define MPK  45          // per-k moment slots

#define LAMBDA_ENERGY 0.1
#define LAMBDA_COV    0.005

#define MOMENT_BLOCKS   296   // 2/SM @~80regs = 41K regs (window 1)
#define RECONSTA_BLOCKS 296   // 2/SM @32regs = 16K regs  (window 1, co-resident)
#define RECONSTB_BLOCKS 888   // 6/SM @32regs             (window 2)
#define ENERGY_BLOCKS   444   // 3/SM                     (window 2, overlaps B)
#define DONE_TARGET     (RECONSTA_BLOCKS + RECONSTB_BLOCKS + ENERGY_BLOCKS)

// ---------------- device scratch (zero-init at load; finalizing block
// re-zeroes everything dirtied each replay) ----------------
__device__ double g_mom[KK * MPK];
__device__ double g_reconst;
__device__ double g_energy;
__device__ double g_base;            // lambda_cov*cov_diag
__device__ float  g_w2[KK * NTRI];
__device__ float  g_bv[KK * DD];
__device__ float  g_cst[KK];
__device__ unsigned g_mctr;          // moments last-block counter
__device__ unsigned g_done;          // completion counter (A + B + energy)

__device__ __constant__ int TRI_ROW[8] = {0, 8, 15, 21, 26, 30, 33, 35};

__device__ __forceinline__ float warp_reduce(float v) {
#pragma unroll
    for (int o = 16; o > 0; o >>= 1) v += __shfl_xor_sync(0xFFFFFFFFu, v, o);
    return v;
}

__device__ __forceinline__ void finish_and_maybe_finalize(float* out) {
    __shared__ unsigned s_last;
    if (threadIdx.x == 0) {
        __threadfence();
        unsigned prev = atomicAdd(&g_done, 1u);
        s_last = (prev == (unsigned)(DONE_TARGET - 1)) ? 1u : 0u;
    }
    __syncthreads();
    if (s_last) {
        if (threadIdx.x == 0) {
            __threadfence();
            double rm = g_reconst / (double)NEL;
            double e  = *((volatile double*)&g_energy);
            out[0] = (float)(rm + g_base + LAMBDA_ENERGY * (e / (double)NS));
            g_reconst = 0.0;
            g_energy = 0.0;
            g_done = 0u;
        }
        for (int i = threadIdx.x; i < KK * MPK; i += blockDim.x) g_mom[i] = 0.0;
    }
}

// ---------------- shared reconst body ----------------
__device__ __forceinline__ void reconst_range(
    const float4* __restrict__ x, const float4* __restrict__ xh,
    int lo, int hi, int nblocks, float* __restrict__ out) {
    float acc0 = 0.0f, acc1 = 0.0f;
    int i = lo + blockIdx.x * 256 + threadIdx.x;
    const int stride = nblocks * 256;
    for (; i + stride < hi; i += 2 * stride) {
        float4 a0 = x[i], b0 = xh[i];
        float4 a1 = x[i + stride], b1 = xh[i + stride];
        float d;
        d = b0.x - a0.x; acc0 = fmaf(d, d, acc0);
        d = b0.y - a0.y; acc0 = fmaf(d, d, acc0);
        d = b0.z - a0.z; acc0 = fmaf(d, d, acc0);
        d = b0.w - a0.w; acc0 = fmaf(d, d, acc0);
        d = b1.x - a1.x; acc1 = fmaf(d, d, acc1);
        d = b1.y - a1.y; acc1 = fmaf(d, d, acc1);
        d = b1.z - a1.z; acc1 = fmaf(d, d, acc1);
        d = b1.w - a1.w; acc1 = fmaf(d, d, acc1);
    }
    for (; i < hi; i += stride) {
        float4 a = x[i], b = xh[i];
        float d;
        d = b.x - a.x; acc0 = fmaf(d, d, acc0);
        d = b.y - a.y; acc0 = fmaf(d, d, acc0);
        d = b.z - a.z; acc0 = fmaf(d, d, acc0);
        d = b.w - a.w; acc0 = fmaf(d, d, acc0);
    }
    __shared__ float red[8];
    float v = warp_reduce(acc0 + acc1);
    int lane = threadIdx.x & 31, wid = threadIdx.x >> 5;
    if (lane == 0) red[wid] = v;
    __syncthreads();
    if (threadIdx.x == 0) {
        float s = 0.0f;
#pragma unroll
        for (int w = 0; w < 8; w++) s += red[w];
        atomicAdd(&g_reconst, (double)s);
    }
    finish_and_maybe_finalize(out);
}

// window 1: low-occupancy slice, co-resident with moments
__global__ void __launch_bounds__(256, 2) reconstA_kernel(
    const float4* __restrict__ x, const float4* __restrict__ xh,
    float* __restrict__ out) {
    reconst_range(x, xh, 0, SPLIT_N4, RECONSTA_BLOCKS, out);
}

// window 2: full-machine remainder
__global__ void __launch_bounds__(256, 6) reconstB_kernel(
    const float4* __restrict__ x, const float4* __restrict__ xh,
    float* __restrict__ out) {
    reconst_range(x, xh, SPLIT_N4, N4, RECONSTB_BLOCKS, out);
}

// ---------------- moments: R12's 2x-unrolled 8-lane scheme -----------------
__global__ void __launch_bounds__(256, 3) moments_kernel(
    const float* __restrict__ z, const float* __restrict__ gamma) {
    const int lane = threadIdx.x & 31;
    const int k = lane & 7;
    const int warp = threadIdx.x >> 5;                 // 0..7
    const int slot = (blockIdx.x * 256 + threadIdx.x) >> 3;
    const int stride = (MOMENT_BLOCKS * 256) >> 3;

    float gs = 0.0f;
    float sz[DD];
    float s2[NTRI];
#pragma unroll
    for (int i = 0; i < DD; i++) sz[i] = 0.0f;
#pragma unroll
    for (int t = 0; t < NTRI; t++) s2[t] = 0.0f;

    int n = slot;
    for (; n + stride < NS; n += 2 * stride) {
        float4 a0 = *reinterpret_cast<const float4*>(z + (size_t)n * 8);
        float4 a1 = *reinterpret_cast<const float4*>(z + (size_t)n * 8 + 4);
        float4 b0 = *reinterpret_cast<const float4*>(z + (size_t)(n + stride) * 8);
        float4 b1 = *reinterpret_cast<const float4*>(z + (size_t)(n + stride) * 8 + 4);
        float ga = __ldg(gamma + (size_t)n * 8 + k);
        float gb = __ldg(gamma + (size_t)(n + stride) * 8 + k);
        {
            float zz[8] = {a0.x, a0.y, a0.z, a0.w, a1.x, a1.y, a1.z, a1.w};
            gs += ga;
            float gz[8];
#pragma unroll
            for (int i = 0; i < 8; i++) { gz[i] = ga * zz[i]; sz[i] += gz[i]; }
            int t = 0;
#pragma unroll
            for (int i = 0; i < 8; i++)
#pragma unroll
                for (int j = i; j < 8; j++) { s2[t] = fmaf(gz[i], zz[j], s2[t]); t++; }
        }
        {
            float zz[8] = {b0.x, b0.y, b0.z, b0.w, b1.x, b1.y, b1.z, b1.w};
            gs += gb;
            float gz[8];
#pragma unroll
            for (int i = 0; i < 8; i++) { gz[i] = gb * zz[i]; sz[i] += gz[i]; }
            int t = 0;
#pragma unroll
            for (int i = 0; i < 8; i++)
#pragma unroll
                for (int j = i; j < 8; j++) { s2[t] = fmaf(gz[i], zz[j], s2[t]); t++; }
        }
    }
    for (; n < NS; n += stride) {
        float4 a0 = *reinterpret_cast<const float4*>(z + (size_t)n * 8);
        float4 a1 = *reinterpret_cast<const float4*>(z + (size_t)n * 8 + 4);
        float g = __ldg(gamma + (size_t)n * 8 + k);
        float zz[8] = {a0.x, a0.y, a0.z, a0.w, a1.x, a1.y, a1.z, a1.w};
        gs += g;
        float gz[8];
#pragma unroll
        for (int i = 0; i < 8; i++) { gz[i] = g * zz[i]; sz[i] += gz[i]; }
        int t = 0;
#pragma unroll
        for (int i = 0; i < 8; i++)
#pragma unroll
            for (int j = i; j < 8; j++) { s2[t] = fmaf(gz[i], zz[j], s2[t]); t++; }
    }

    const unsigned m = 0xFFFFFFFFu;
    gs += __shfl_xor_sync(m, gs, 8);  gs += __shfl_xor_sync(m, gs, 16);
#pragma unroll
    for (int i = 0; i < DD; i++) {
        sz[i] += __shfl_xor_sync(m, sz[i], 8);
        sz[i] += __shfl_xor_sync(m, sz[i], 16);
    }
#pragma unroll
    for (int t = 0; t < NTRI; t++) {
        s2[t] += __shfl_xor_sync(m, s2[t], 8);
        s2[t] += __shfl_xor_sync(m, s2[t], 16);
    }

    __shared__ float sacc[8][KK * MPK];   // 11.5 KB
    if (lane < 8) {
        float* p = &sacc[warp][k * MPK];
        p[0] = gs;
#pragma unroll
        for (int i = 0; i < DD; i++) p[1 + i] = sz[i];
#pragma unroll
        for (int t = 0; t < NTRI; t++) p[9 + t] = s2[t];
    }
    __syncthreads();

    for (int i = threadIdx.x; i < KK * MPK; i += 256) {
        float v = 0.0f;
#pragma unroll
        for (int w = 0; w < 8; w++) v += sacc[w][i];
        atomicAdd(&g_mom[i], (double)v);
    }

    // ---- last block runs stats inline (warp per component) ----
    __shared__ bool is_last;
    __threadfence();
    __syncthreads();
    if (threadIdx.x == 0) {
        unsigned prev = atomicAdd(&g_mctr, 1u);
        is_last = (prev == (unsigned)(gridDim.x - 1));
        if (is_last) g_mctr = 0u;
    }
    __syncthreads();
    if (!is_last) return;
    __threadfence();

    {
        const int w = warp;
        const int r = lane;
        __shared__ float s_cd[8];

        const double* mo = g_mom + w * MPK;
        const float gsf = (float)mo[0];
        const float rgs = 1.0f / gsf;

        float mu[8];
#pragma unroll
        for (int j = 0; j < 8; j++) mu[j] = (float)mo[1 + j] * rgs;

        float ar[8], ir[8];
        float cd = 0.0f;
        if (r < 8) {
#pragma unroll
            for (int j = 0; j < 8; j++) {
                int i0 = r < j ? r : j;
                int j0 = r < j ? j : r;
                int t = TRI_ROW[i0] + (j0 - i0);
                ar[j] = fmaf(-mu[r], mu[j], (float)mo[9 + t] * rgs);
                ir[j] = (r == j) ? 1.0f : 0.0f;
            }
            ar[r] += 1e-12f;
            cd = 1.0f / ar[r];
        } else {
#pragma unroll
            for (int j = 0; j < 8; j++) { ar[j] = (r == j + 24) ? 1.0f : 0.0f; ir[j] = 0.0f; }
        }

        float det = 1.0f;
#pragma unroll
        for (int p = 0; p < 8; p++) {
            float piv = __shfl_sync(m, ar[p], p);
            det *= piv;
            float rc = 1.0f / piv;
            float par[8], pir[8];
#pragma unroll
            for (int j = 0; j < 8; j++) par[j] = __shfl_sync(m, ar[j], p) * rc;
#pragma unroll
            for (int j = 0; j < 8; j++) pir[j] = __shfl_sync(m, ir[j], p) * rc;
            float f = ar[p];
            if (r == p) {
#pragma unroll
                for (int j = 0; j < 8; j++) { ar[j] = par[j]; ir[j] = pir[j]; }
            } else {
#pragma unroll
                for (int j = 0; j < 8; j++) {
                    ar[j] = fmaf(-f, par[j], ar[j]);
                    ir[j] = fmaf(-f, pir[j], ir[j]);
                }
            }
        }

        float cstp = 0.0f;
        if (r < 8) {
#pragma unroll
            for (int j = 0; j < 8; j++) {
                if (j >= r) {
                    int t = TRI_ROW[r] + (j - r);
                    g_w2[w * NTRI + t] = (j == r) ? (-0.5f * ir[r]) : (-ir[j]);
                }
            }
            float b = 0.0f;
#pragma unroll
            for (int j = 0; j < 8; j++) b = fmaf(ir[j], mu[j], b);
            g_bv[w * DD + r] = b;
            cstp = b * mu[r];
        }
#pragma unroll
        for (int o = 4; o > 0; o >>= 1) {
            cstp += __shfl_xor_sync(m, cstp, o);
            cd   += __shfl_xor_sync(m, cd, o);
        }
        if (r == 0) {
            float phi = gsf * (1.0f / (float)NS);
            float ck = phi / (39.478417604357434f * sqrtf(sqrtf(det)));
            g_cst[w] = -0.5f * cstp + logf(ck);
            s_cd[w] = cd;
        }
        __syncthreads();
        if (threadIdx.x == 0) {
            float cdt = 0.0f;
#pragma unroll
            for (int i = 0; i < 8; i++) cdt += s_cd[i];
            g_base = LAMBDA_COV * (double)cdt;
        }
    }
}

// ---------------- energy: R12's 2x unrolled version ------------------------
__global__ void __launch_bounds__(256, 3) energy_kernel(const float* __restrict__ z,
                                                        float* __restrict__ out) {
    const int lane = threadIdx.x & 31;
    const int k = lane & 7;

    float w[NTRI], bv[DD], cst;
#pragma unroll
    for (int t = 0; t < NTRI; t++) w[t] = g_w2[k * NTRI + t];
#pragma unroll
    for (int i = 0; i < DD; i++) bv[i] = g_bv[k * DD + i];
    cst = g_cst[k];

    const int slot = (blockIdx.x * blockDim.x + threadIdx.x) >> 3;
    const int stride = (gridDim.x * blockDim.x) >> 3;
    const unsigned m = 0xFFFFFFFFu;

    float acc = 0.0f;
    int n = slot;
    for (; n + stride < NS; n += 2 * stride) {
        float4 a0 = *reinterpret_cast<const float4*>(z + (size_t)n * 8);
        float4 a1 = *reinterpret_cast<const float4*>(z + (size_t)n * 8 + 4);
        float4 b0 = *reinterpret_cast<const float4*>(z + (size_t)(n + stride) * 8);
        float4 b1 = *reinterpret_cast<const float4*>(z + (size_t)(n + stride) * 8 + 4);
        {
            float zz[8] = {a0.x, a0.y, a0.z, a0.w, a1.x, a1.y, a1.z, a1.w};
            float qv = cst;
            int t = 0;
#pragma unroll
            for (int i = 0; i < 8; i++) {
                float row = bv[i];
#pragma unroll
                for (int j = i; j < 8; j++) { row = fmaf(w[t], zz[j], row); t++; }
                qv = fmaf(zz[i], row, qv);
            }
            float e = __expf(qv);
            e += __shfl_xor_sync(m, e, 1);
            e += __shfl_xor_sync(m, e, 2);
            e += __shfl_xor_sync(m, e, 4);
            if (k == 0) acc += -__logf(e + 1e-12f);
        }
        {
            float zz[8] = {b0.x, b0.y, b0.z, b0.w, b1.x, b1.y, b1.z, b1.w};
            float qv = cst;
            int t = 0;
#pragma unroll
            for (int i = 0; i < 8; i++) {
                float row = bv[i];
#pragma unroll
                for (int j = i; j < 8; j++) { row = fmaf(w[t], zz[j], row); t++; }
                qv = fmaf(zz[i], row, qv);
            }
            float e = __expf(qv);
            e += __shfl_xor_sync(m, e, 1);
            e += __shfl_xor_sync(m, e, 2);
            e += __shfl_xor_sync(m, e, 4);
            if (k == 0) acc += -__logf(e + 1e-12f);
        }
    }
    for (; n < NS; n += stride) {
        float4 a0 = *reinterpret_cast<const float4*>(z + (size_t)n * 8);
        float4 a1 = *reinterpret_cast<const float4*>(z + (size_t)n * 8 + 4);
        float zz[8] = {a0.x, a0.y, a0.z, a0.w, a1.x, a1.y, a1.z, a1.w};
        float qv = cst;
        int t = 0;
#pragma unroll
        for (int i = 0; i < 8; i++) {
            float row = bv[i];
#pragma unroll
            for (int j = i; j < 8; j++) { row = fmaf(w[t], zz[j], row); t++; }
            qv = fmaf(zz[i], row, qv);
        }
        float e = __expf(qv);
        e += __shfl_xor_sync(m, e, 1);
        e += __shfl_xor_sync(m, e, 2);
        e += __shfl_xor_sync(m, e, 4);
        if (k == 0) acc += -__logf(e + 1e-12f);
    }

    __shared__ float red[8];
    float v = warp_reduce(acc);
    int wid = threadIdx.x >> 5;
    if (lane == 0) red[wid] = v;
    __syncthreads();
    if (threadIdx.x == 0) {
        float s = 0.0f;
#pragma unroll
        for (int i = 0; i < 8; i++) s += red[i];
        atomicAdd(&g_energy, (double)s);
    }
    finish_and_maybe_finalize(out);
}

// ---------------- launch: two windows --------------------------------------
// Window 1: moments (2/SM) || reconstA (2/SM) — both fit (57K regs)
// Window 2: energy (3/SM) || reconstB (6/SM) — self-balancing placement
static cudaStream_t s_side = nullptr;
static cudaEvent_t s_fork = nullptr, s_join = nullptr;

extern "C" void kernel_launch(void* const* d_in, const int* in_sizes, int n_in,
                              void* d_out, int out_size) {
    const float* x     = (const float*)d_in[0];
    const float* xh    = (const float*)d_in[1];
    const float* z     = (const float*)d_in[2];
    const float* gamma = (const float*)d_in[3];
    float* out = (float*)d_out;

    if (s_side == nullptr) {
        cudaStreamCreateWithFlags(&s_side, cudaStreamNonBlocking);
        cudaEventCreateWithFlags(&s_fork, cudaEventDisableTiming);
        cudaEventCreateWithFlags(&s_join, cudaEventDisableTiming);
    }

    cudaEventRecord(s_fork, 0);
    cudaStreamWaitEvent(s_side, s_fork, 0);
    // side: moments then energy (energy needs moments' stats)
    moments_kernel<<<MOMENT_BLOCKS, 256, 0, s_side>>>(z, gamma);
    energy_kernel<<<ENERGY_BLOCKS, 256, 0, s_side>>>(z, out);
    // main: reconstA co-resident with moments, then reconstB takes the machine
    reconstA_kernel<<<RECONSTA_BLOCKS, 256>>>((const float4*)x, (const float4*)xh, out);
    reconstB_kernel<<<RECONSTB_BLOCKS, 256>>>((const float4*)x, (const float4*)xh, out);
    cudaEventRecord(s_join, s_side);
    cudaStreamWaitEvent(0, s_join, 0);
}